// round 13
// baseline (speedup 1.0000x reference)
#include <cuda_runtime.h>
#include <cuda_bf16.h>

// PLIF neuron scan, T=8. x: [B=32,T=8,S=131072] fp32 -> spikes same shape.
// Sustained mixed-stream DRAM-bound (~5.7 TB/s plateau; invariant under MLP,
// occupancy, cache policy, L2 residency hints, access width, stream shape).
//
// R13 (= R12 resubmit, infra failure): single-wave persistent grid.
// 512 CTAs x 256 threads (regs ~52 -> 4 CTAs/SM resident -> exactly one
// wave, zero wave transitions, no ragged tail). Each thread processes 8
// float4 sites; per site the proven R3 body: 8 timestep loads front-batched
// (MLP=8), register scan, per-step store.

#define VTH 0.5f
#define S4C 32768u      // spatial float4 per (b,t) = 128*32*32/4
#define S4_SHIFT 15
#define S4_MASK 32767
#define NTHREADS 131072u   // 512 * 256
#define NSITES 1048576u    // total float4 sites; NSITES/NTHREADS = 8 exact

__global__ __launch_bounds__(256) void plif_kernel(
    const float4* __restrict__ x,
    const float* __restrict__ w,
    float4* __restrict__ out)
{
    unsigned tid0 = blockIdx.x * 256u + threadIdx.x;   // 0..131071

    float wv = __ldg(w);
    float tau = 1.0f / (1.0f + __expf(-wv));

#pragma unroll 1
    for (unsigned it = 0; it < 8; it++) {
        unsigned i = tid0 + it * NTHREADS;             // site index
        unsigned b = i >> S4_SHIFT;
        unsigned s = i & S4_MASK;
        unsigned base = (b << 3) * S4C + s;            // (b, t=0, s)
        const float4* px = x + base;
        float4* po = out + base;

        // Front-batch all 8 timestep loads -> MLP=8.
        float4 xv[8];
#pragma unroll
        for (int t = 0; t < 8; t++) {
            xv[t] = __ldcs(px + t * S4C);
        }

        // Sequential membrane scan; store each spike vector immediately.
        float4 m = make_float4(0.f, 0.f, 0.f, 0.f);
#pragma unroll
        for (int t = 0; t < 8; t++) {
            float4 r;

            m.x = fmaf(tau, m.x, xv[t].x);
            r.x = (m.x > VTH) ? 1.0f : 0.0f;
            m.x = (m.x > VTH) ? 0.0f : m.x;

            m.y = fmaf(tau, m.y, xv[t].y);
            r.y = (m.y > VTH) ? 1.0f : 0.0f;
            m.y = (m.y > VTH) ? 0.0f : m.y;

            m.z = fmaf(tau, m.z, xv[t].z);
            r.z = (m.z > VTH) ? 1.0f : 0.0f;
            m.z = (m.z > VTH) ? 0.0f : m.z;

            m.w = fmaf(tau, m.w, xv[t].w);
            r.w = (m.w > VTH) ? 1.0f : 0.0f;
            m.w = (m.w > VTH) ? 0.0f : m.w;

            __stcs(po + t * S4C, r);
        }
    }
}

extern "C" void kernel_launch(void* const* d_in, const int* in_sizes, int n_in,
                              void* d_out, int out_size) {
    const float4* x = (const float4*)d_in[0];
    const float* w = (const float*)d_in[1];
    float4* o = (float4*)d_out;

    // Single wave: 512 CTAs x 256 threads; each thread does 8 sites.
    plif_kernel<<<512, 256>>>(x, w, o);
}

// round 14
// speedup vs baseline: 1.1776x; 1.1776x over previous
#include <cuda_runtime.h>
#include <cuda_bf16.h>

// PLIF neuron scan, T=8. x: [B=32,T=8,S=131072] fp32 -> spikes same shape.
// FINAL (champion R3 configuration).
//
// 268 MB irreducible streaming traffic; binding constraint is the sustained
// mixed read/write DRAM rate (~5.7-5.9 TB/s plateau, shown invariant across
// MLP 4-16, occupancy 26-84%, all L1/L2 cache & residency policies, 128/256b
// access width, stream shape, and wave structure over rounds 1-13).
//
// Structure: one thread = one float4 site (4 contiguous floats x 8
// timesteps). The 8 timestep loads are independent of the membrane
// recurrence -> front-batched for MLP=8; the sequential scan runs in
// registers; each spike vector stores immediately (keeps regs at 52, no
// spill, 4 CTAs/SM). 4096 CTAs oversubscribe the chip ~7 waves deep, which
// self-balances across SMs (single-wave variant regressed 14%).

#define VTH 0.5f
#define S4C 32768u      // spatial float4 per (b,t) = 128*32*32/4
#define S4_SHIFT 15
#define S4_MASK 32767

__global__ __launch_bounds__(256) void plif_kernel(
    const float4* __restrict__ x,
    const float* __restrict__ w,
    float4* __restrict__ out)
{
    unsigned i = blockIdx.x * 256u + threadIdx.x;   // 0..1048575 exact
    unsigned b = i >> S4_SHIFT;
    unsigned s = i & S4_MASK;

    float wv = __ldg(w);
    float tau = 1.0f / (1.0f + __expf(-wv));

    unsigned base = (b << 3) * S4C + s;             // (b, t=0, s)
    const float4* px = x + base;
    float4* po = out + base;

    // Front-batch all 8 timestep loads (independent of the scan) -> MLP=8.
    float4 xv[8];
#pragma unroll
    for (int t = 0; t < 8; t++) {
        xv[t] = __ldcs(px + t * S4C);
    }

    // Sequential membrane scan; store each spike vector immediately.
    float4 m = make_float4(0.f, 0.f, 0.f, 0.f);
#pragma unroll
    for (int t = 0; t < 8; t++) {
        float4 r;

        m.x = fmaf(tau, m.x, xv[t].x);
        r.x = (m.x > VTH) ? 1.0f : 0.0f;
        m.x = (m.x > VTH) ? 0.0f : m.x;

        m.y = fmaf(tau, m.y, xv[t].y);
        r.y = (m.y > VTH) ? 1.0f : 0.0f;
        m.y = (m.y > VTH) ? 0.0f : m.y;

        m.z = fmaf(tau, m.z, xv[t].z);
        r.z = (m.z > VTH) ? 1.0f : 0.0f;
        m.z = (m.z > VTH) ? 0.0f : m.z;

        m.w = fmaf(tau, m.w, xv[t].w);
        r.w = (m.w > VTH) ? 1.0f : 0.0f;
        m.w = (m.w > VTH) ? 0.0f : m.w;

        __stcs(po + t * S4C, r);
    }
}

extern "C" void kernel_launch(void* const* d_in, const int* in_sizes, int n_in,
                              void* d_out, int out_size) {
    const float4* x = (const float4*)d_in[0];
    const float* w = (const float*)d_in[1];
    float4* o = (float4*)d_out;

    // 1,048,576 float4 sites -> exact 4096 x 256 grid
    plif_kernel<<<4096, 256>>>(x, w, o);
}